// round 1
// baseline (speedup 1.0000x reference)
#include <cuda_runtime.h>
#include <cuda_bf16.h>
#include <mma.h>

using namespace nvcuda;

#define B_ 8
#define T_ 256
#define S_ 400
#define H_ 512
#define V_ 32000
#define R_ 2048   // B*T rows

// ---- scratch (no cudaMalloc allowed -> __device__ globals) ----
__device__ float          g_exp[(size_t)R_ * V_];      // 262 MB: exp(logits)
__device__ __nv_bfloat16  g_w2b[(size_t)H_ * V_];      // 32.8 MB: bf16 w2
__device__ __nv_bfloat16  g_hidden[R_ * H_];           // 2 MB: bf16 hidden
__device__ float          g_pgen[R_];
__device__ float          g_rowsum[R_];

// ---------------------------------------------------------------------------
// K1: p_gen = sigmoid(state_input @ w_pgen + b_pgen); also zero row sums.
// One warp per row.
// ---------------------------------------------------------------------------
__global__ void pgen_kernel(const float* __restrict__ state,
                            const float* __restrict__ wp,
                            const float* __restrict__ bp) {
    int row  = blockIdx.x * 8 + (threadIdx.x >> 5);
    int lane = threadIdx.x & 31;
    const float* x = state + (size_t)row * (2 * H_);
    float s = 0.f;
    #pragma unroll 8
    for (int i = lane; i < 2 * H_; i += 32) s += x[i] * wp[i];
    #pragma unroll
    for (int o = 16; o; o >>= 1) s += __shfl_xor_sync(0xffffffffu, s, o);
    if (lane == 0) {
        float z = s + bp[0];
        g_pgen[row]   = 1.f / (1.f + __expf(-z));
        g_rowsum[row] = 0.f;
    }
}

// ---------------------------------------------------------------------------
// K2: convert w2 (fp32, 512x32000) -> bf16
// ---------------------------------------------------------------------------
__global__ void conv_w2_kernel(const float* __restrict__ w2) {
    int i = blockIdx.x * blockDim.x + threadIdx.x;   // 0 .. 4095999 (float4s)
    float4 v = ((const float4*)w2)[i];
    __nv_bfloat162* dst = (__nv_bfloat162*)g_w2b;
    dst[2 * i]     = __floats2bfloat162_rn(v.x, v.y);
    dst[2 * i + 1] = __floats2bfloat162_rn(v.z, v.w);
}

// ---------------------------------------------------------------------------
// K3: hidden = s_output @ w1 + b1  (2048x512x512, fp32 compute, bf16 out)
// 64x64 tile, 256 threads, 4x4 per thread.
// ---------------------------------------------------------------------------
__global__ void hidden_kernel(const float* __restrict__ A,
                              const float* __restrict__ W,
                              const float* __restrict__ b1) {
    __shared__ float As[16][65];   // [k][m]
    __shared__ float Bs[16][65];   // [k][n]
    int tx = threadIdx.x & 15, ty = threadIdx.x >> 4;
    int m0 = blockIdx.y * 64, n0 = blockIdx.x * 64;
    float acc[4][4] = {};
    for (int kk = 0; kk < H_; kk += 16) {
        for (int i = threadIdx.x; i < 1024; i += 256) {
            int r = i >> 4, c = i & 15;
            As[c][r] = A[(size_t)(m0 + r) * H_ + kk + c];
        }
        for (int i = threadIdx.x; i < 1024; i += 256) {
            int r = i >> 6, c = i & 63;
            Bs[r][c] = W[(size_t)(kk + r) * H_ + n0 + c];
        }
        __syncthreads();
        #pragma unroll
        for (int k = 0; k < 16; k++) {
            float a[4], bb[4];
            #pragma unroll
            for (int i = 0; i < 4; i++) a[i] = As[k][ty * 4 + i];
            #pragma unroll
            for (int j = 0; j < 4; j++) bb[j] = Bs[k][tx * 4 + j];
            #pragma unroll
            for (int i = 0; i < 4; i++)
                #pragma unroll
                for (int j = 0; j < 4; j++) acc[i][j] += a[i] * bb[j];
        }
        __syncthreads();
    }
    #pragma unroll
    for (int i = 0; i < 4; i++)
        #pragma unroll
        for (int j = 0; j < 4; j++) {
            int rr = m0 + ty * 4 + i, cc = n0 + tx * 4 + j;
            g_hidden[rr * H_ + cc] = __float2bfloat16(acc[i][j] + b1[cc]);
        }
}

// ---------------------------------------------------------------------------
// K4: big GEMM (2048x32000x512) bf16 WMMA, fp32 accum, fused epilogue:
//     e = exp(logit + b2);  write e to g_exp;  accumulate per-row sums.
// CTA tile 128x128, BK=32, 8 warps (2x4), each warp 64x32 = 4x2 wmma frags.
// ---------------------------------------------------------------------------
__global__ void logits_kernel(const float* __restrict__ b2) {
    __shared__ __nv_bfloat16 As[128][48];   // ld 48 (96B, 16B-aligned rows)
    __shared__ __nv_bfloat16 Bs[32][144];   // ld 144 (288B)
    __shared__ float fragbuf[8][320];       // per-warp 16x20 staging
    __shared__ float rowsum_sm[128];

    int tid = threadIdx.x, wid = tid >> 5, lane = tid & 31;
    int warpM = wid >> 2, warpN = wid & 3;
    int n0 = blockIdx.x * 128, m0 = blockIdx.y * 128;

    wmma::fragment<wmma::accumulator, 16, 16, 16, float> c[4][2];
    #pragma unroll
    for (int i = 0; i < 4; i++)
        #pragma unroll
        for (int j = 0; j < 2; j++) wmma::fill_fragment(c[i][j], 0.f);

    for (int kk = 0; kk < H_; kk += 32) {
        #pragma unroll
        for (int it = 0; it < 2; it++) {
            int i = tid + it * 256;
            int r = i >> 2, c4 = i & 3;
            *(uint4*)(&As[r][c4 * 8]) =
                *(const uint4*)(&g_hidden[(size_t)(m0 + r) * H_ + kk + c4 * 8]);
        }
        #pragma unroll
        for (int it = 0; it < 2; it++) {
            int i = tid + it * 256;
            int r = i >> 4, c4 = i & 15;
            *(uint4*)(&Bs[r][c4 * 8]) =
                *(const uint4*)(&g_w2b[(size_t)(kk + r) * V_ + n0 + c4 * 8]);
        }
        __syncthreads();
        #pragma unroll
        for (int ks = 0; ks < 2; ks++) {
            wmma::fragment<wmma::matrix_a, 16, 16, 16, __nv_bfloat16, wmma::row_major> a[4];
            wmma::fragment<wmma::matrix_b, 16, 16, 16, __nv_bfloat16, wmma::row_major> bf[2];
            #pragma unroll
            for (int i = 0; i < 4; i++)
                wmma::load_matrix_sync(a[i], &As[warpM * 64 + i * 16][ks * 16], 48);
            #pragma unroll
            for (int j = 0; j < 2; j++)
                wmma::load_matrix_sync(bf[j], &Bs[ks * 16][warpN * 32 + j * 16], 144);
            #pragma unroll
            for (int i = 0; i < 4; i++)
                #pragma unroll
                for (int j = 0; j < 2; j++)
                    wmma::mma_sync(c[i][j], a[i], bf[j], c[i][j]);
        }
        __syncthreads();
    }

    if (tid < 128) rowsum_sm[tid] = 0.f;
    __syncthreads();

    float* buf = fragbuf[wid];
    int r = lane >> 1;
    int cbase = (lane & 1) * 8;
    #pragma unroll
    for (int i = 0; i < 4; i++) {
        #pragma unroll
        for (int j = 0; j < 2; j++) {
            wmma::store_matrix_sync(buf, c[i][j], 20, wmma::mem_row_major);
            __syncwarp();
            int lrow = warpM * 64 + i * 16 + r;
            int grow = m0 + lrow;
            int gcol = n0 + warpN * 32 + j * 16 + cbase;
            float s = 0.f, vals[8];
            #pragma unroll
            for (int cc = 0; cc < 8; cc++) {
                float v = buf[r * 20 + cbase + cc] + b2[gcol + cc];
                v = __expf(v);
                vals[cc] = v;
                s += v;
            }
            float* dst = &g_exp[(size_t)grow * V_ + gcol];
            ((float4*)dst)[0] = make_float4(vals[0], vals[1], vals[2], vals[3]);
            ((float4*)dst)[1] = make_float4(vals[4], vals[5], vals[6], vals[7]);
            s += __shfl_xor_sync(0xffffffffu, s, 1);
            if ((lane & 1) == 0) atomicAdd(&rowsum_sm[lrow], s);
            __syncwarp();
        }
    }
    __syncthreads();
    if (tid < 128) atomicAdd(&g_rowsum[m0 + tid], rowsum_sm[tid]);
}

// ---------------------------------------------------------------------------
// K5: final: out = log(p*exp/sum + (1-p)*scatter(attn) + 1e-12)
// One CTA per row; scatter handled by smem hash table + bitmap prefilter.
// ---------------------------------------------------------------------------
__device__ __forceinline__ float hash_lookup(int idx, const int* keys, const float* vals) {
    int h = idx & 1023;
    while (keys[h] != idx) h = (h + 1) & 1023;
    return vals[h];
}

__global__ void final_kernel(const float* __restrict__ attn,
                             const int* __restrict__ ebev,
                             float* __restrict__ out) {
    __shared__ unsigned bitmap[1000];   // 32000 bits
    __shared__ int keys[1024];
    __shared__ float vals[1024];
    int row = blockIdx.x;
    int b = row >> 8;                   // T_ = 256
    int tid = threadIdx.x;
    for (int i = tid; i < 1000; i += 256) bitmap[i] = 0u;
    for (int i = tid; i < 1024; i += 256) { keys[i] = -1; vals[i] = 0.f; }
    __syncthreads();
    float p = g_pgen[row];
    float omp = 1.f - p;
    float scale = p / g_rowsum[row];
    for (int s = tid; s < S_; s += 256) {
        int idx = ebev[b * S_ + s];
        float v = omp * attn[(size_t)row * S_ + s];
        atomicOr(&bitmap[idx >> 5], 1u << (idx & 31));
        int h = idx & 1023;
        while (true) {
            int old = atomicCAS(&keys[h], -1, idx);
            if (old == -1 || old == idx) { atomicAdd(&vals[h], v); break; }
            h = (h + 1) & 1023;
        }
    }
    __syncthreads();
    const float4* erow = (const float4*)&g_exp[(size_t)row * V_];
    float4* orow = (float4*)&out[(size_t)row * V_];
    for (int q = tid; q < V_ / 4; q += 256) {
        float4 e = erow[q];
        int vbase = q * 4;
        unsigned w = (bitmap[vbase >> 5] >> (vbase & 31)) & 0xFu;
        float f0 = e.x * scale + 1e-12f;
        float f1 = e.y * scale + 1e-12f;
        float f2 = e.z * scale + 1e-12f;
        float f3 = e.w * scale + 1e-12f;
        if (w) {
            if (w & 1u) f0 += hash_lookup(vbase + 0, keys, vals);
            if (w & 2u) f1 += hash_lookup(vbase + 1, keys, vals);
            if (w & 4u) f2 += hash_lookup(vbase + 2, keys, vals);
            if (w & 8u) f3 += hash_lookup(vbase + 3, keys, vals);
        }
        orow[q] = make_float4(__logf(f0), __logf(f1), __logf(f2), __logf(f3));
    }
}

// ---------------------------------------------------------------------------
extern "C" void kernel_launch(void* const* d_in, const int* in_sizes, int n_in,
                              void* d_out, int out_size) {
    const float* s_output = (const float*)d_in[0];
    const float* state    = (const float*)d_in[1];
    const float* attn     = (const float*)d_in[2];
    const int*   ebev     = (const int*)d_in[3];
    const float* w_pgen   = (const float*)d_in[4];
    const float* b_pgen   = (const float*)d_in[5];
    const float* w1       = (const float*)d_in[6];
    const float* b1       = (const float*)d_in[7];
    const float* w2       = (const float*)d_in[8];
    const float* b2       = (const float*)d_in[9];
    float* out = (float*)d_out;

    pgen_kernel<<<R_ / 8, 256>>>(state, w_pgen, b_pgen);
    conv_w2_kernel<<<(H_ * V_ / 4) / 256, 256>>>(w2);
    hidden_kernel<<<dim3(H_ / 64, R_ / 64), 256>>>(s_output, w1, b1);
    logits_kernel<<<dim3(V_ / 128, R_ / 128), 256>>>(b2);
    final_kernel<<<R_, 256>>>(attn, ebev, out);
}

// round 6
// speedup vs baseline: 1.3823x; 1.3823x over previous
#include <cuda_runtime.h>
#include <cuda_bf16.h>
#include <cuda_fp16.h>
#include <mma.h>
#include <cstdint>

using namespace nvcuda;

#define B_ 8
#define T_ 256
#define S_ 400
#define H_ 512
#define V_ 32000
#define R_ 2048   // B*T rows

// ---- scratch (no cudaMalloc allowed -> __device__ globals) ----
__device__ __half          g_exph[(size_t)R_ * V_];   // 131 MB: exp(logits) fp16
__device__ __nv_bfloat16   g_w2t[(size_t)V_ * H_];    // 32.8 MB: w2 transposed [V][H] bf16
__device__ __nv_bfloat16   g_hidden[R_ * H_];         // 2 MB: bf16 hidden
__device__ float           g_pgen[R_];
__device__ float           g_rowsum[R_];

// ---- cp.async helpers ----
__device__ __forceinline__ uint32_t smem_u32(const void* p) {
    uint32_t a;
    asm("{ .reg .u64 t; cvta.to.shared.u64 t, %1; cvt.u32.u64 %0, t; }" : "=r"(a) : "l"(p));
    return a;
}
__device__ __forceinline__ void cp16(uint32_t dst, const void* src) {
    asm volatile("cp.async.cg.shared.global [%0], [%1], 16;" :: "r"(dst), "l"(src));
}
__device__ __forceinline__ void cp_commit() { asm volatile("cp.async.commit_group;"); }
__device__ __forceinline__ void cp_wait1() { asm volatile("cp.async.wait_group 1;" ::: "memory"); }
__device__ __forceinline__ void cp_wait0() { asm volatile("cp.async.wait_group 0;" ::: "memory"); }

// ===========================================================================
// K1: p_gen = sigmoid(state_input @ w_pgen + b_pgen); zero row sums.
// ===========================================================================
__global__ void pgen_kernel(const float* __restrict__ state,
                            const float* __restrict__ wp,
                            const float* __restrict__ bp) {
    int row  = blockIdx.x * 8 + (threadIdx.x >> 5);
    int lane = threadIdx.x & 31;
    const float* x = state + (size_t)row * (2 * H_);
    float s = 0.f;
    #pragma unroll 8
    for (int i = lane; i < 2 * H_; i += 32) s += x[i] * wp[i];
    #pragma unroll
    for (int o = 16; o; o >>= 1) s += __shfl_xor_sync(0xffffffffu, s, o);
    if (lane == 0) {
        float z = s + bp[0];
        g_pgen[row]   = 1.f / (1.f + __expf(-z));
        g_rowsum[row] = 0.f;
    }
}

// ===========================================================================
// K2: transpose w2 [H][V] fp32 -> g_w2t [V][H] bf16 (K-major B for the GEMM)
// ===========================================================================
__global__ void transpose_w2_kernel(const float* __restrict__ w2) {
    __shared__ float tile[32][33];
    int c0 = blockIdx.x * 32;   // vocab base
    int r0 = blockIdx.y * 32;   // H base
    int tx = threadIdx.x & 31, ty = threadIdx.x >> 5;  // 32 x 8
    #pragma unroll
    for (int i = 0; i < 4; i++)
        tile[ty + i * 8][tx] = w2[(size_t)(r0 + ty + i * 8) * V_ + c0 + tx];
    __syncthreads();
    #pragma unroll
    for (int i = 0; i < 4; i++)
        g_w2t[(size_t)(c0 + ty + i * 8) * H_ + r0 + tx] =
            __float2bfloat16(tile[tx][ty + i * 8]);
}

// ===========================================================================
// K3: hidden = s_output @ w1 + b1  (2048x512x512 fp32 -> bf16)
// ===========================================================================
__global__ void hidden_kernel(const float* __restrict__ A,
                              const float* __restrict__ W,
                              const float* __restrict__ b1) {
    __shared__ float As[16][65];
    __shared__ float Bs[16][65];
    int tx = threadIdx.x & 15, ty = threadIdx.x >> 4;
    int m0 = blockIdx.y * 64, n0 = blockIdx.x * 64;
    float acc[4][4] = {};
    for (int kk = 0; kk < H_; kk += 16) {
        for (int i = threadIdx.x; i < 1024; i += 256) {
            int r = i >> 4, c = i & 15;
            As[c][r] = A[(size_t)(m0 + r) * H_ + kk + c];
        }
        for (int i = threadIdx.x; i < 1024; i += 256) {
            int r = i >> 6, c = i & 63;
            Bs[r][c] = W[(size_t)(kk + r) * H_ + n0 + c];
        }
        __syncthreads();
        #pragma unroll
        for (int k = 0; k < 16; k++) {
            float a[4], bb[4];
            #pragma unroll
            for (int i = 0; i < 4; i++) a[i] = As[k][ty * 4 + i];
            #pragma unroll
            for (int j = 0; j < 4; j++) bb[j] = Bs[k][tx * 4 + j];
            #pragma unroll
            for (int i = 0; i < 4; i++)
                #pragma unroll
                for (int j = 0; j < 4; j++) acc[i][j] += a[i] * bb[j];
        }
        __syncthreads();
    }
    #pragma unroll
    for (int i = 0; i < 4; i++)
        #pragma unroll
        for (int j = 0; j < 4; j++) {
            int rr = m0 + ty * 4 + i, cc = n0 + tx * 4 + j;
            g_hidden[rr * H_ + cc] = __float2bfloat16(acc[i][j] + b1[cc]);
        }
}

// ===========================================================================
// K4: WMMA GEMM (2048 x 32000 x 512, bf16, fp32 accum) + fused epilogue:
//     e = exp(logit + b2) -> g_exph (fp16), rowsums via atomics.
// CTA tile 128x128, BK=64, cp.async double-buffered, 8 warps (2Mx4N),
// warp tile 64x32. Smem ld = 72 elems (144B): ldmatrix row offsets mod 128
// = {0,16,...,112} -> conflict-free. A tile: g_hidden [m][k]; B tile:
// g_w2t [n][k] consumed as wmma col_major matrix_b.
// ===========================================================================
#define LDP  72                       // padded leading dim (elements)
#define CHB  (128 * LDP * 2)          // 18432 B per tile buffer
#define SM_A 0                        // 2 buffers: A0, A1
#define SM_B (2 * CHB)                // 2 buffers: B0, B1
#define GSMEM (4 * CHB)               // 73728 B

__global__ void __launch_bounds__(256, 2)
logits_wmma_kernel(const float* __restrict__ b2) {
    extern __shared__ char sm[];
    uint32_t sb = smem_u32(sm);
    float* stage = (float*)sm;                   // epilogue reuse of A buffers
    float* rowsum_sm = (float*)(sm + 10240);     // still inside A buffer 0

    int tid = threadIdx.x, wid = tid >> 5, lane = tid & 31;
    int warpM = wid >> 2, warpN = wid & 3;
    int n0 = blockIdx.x * 128, m0 = blockIdx.y * 128;

    wmma::fragment<wmma::accumulator, 16, 16, 16, float> c[4][2];
    #pragma unroll
    for (int i = 0; i < 4; i++)
        #pragma unroll
        for (int j = 0; j < 2; j++) wmma::fill_fragment(c[i][j], 0.f);

    // ---- chunk loader: 128 rows x 64 k-els (128B) for both A and B ----
    auto load_chunk = [&](int kc, int buf) {
        #pragma unroll
        for (int h = 0; h < 4; h++) {
            int idx = tid + h * 256;             // 0..1023
            int r = idx >> 3, c16 = idx & 7;
            cp16(sb + SM_A + buf * CHB + r * (LDP * 2) + c16 * 16,
                 &g_hidden[(size_t)(m0 + r) * H_ + kc * 64 + c16 * 8]);
        }
        #pragma unroll
        for (int h = 0; h < 4; h++) {
            int idx = tid + h * 256;
            int r = idx >> 3, c16 = idx & 7;
            cp16(sb + SM_B + buf * CHB + r * (LDP * 2) + c16 * 16,
                 &g_w2t[(size_t)(n0 + r) * H_ + kc * 64 + c16 * 8]);
        }
        cp_commit();
    };

    load_chunk(0, 0);
    load_chunk(1, 1);

    const __nv_bfloat16* Asm = (const __nv_bfloat16*)(sm + SM_A);
    const __nv_bfloat16* Bsm = (const __nv_bfloat16*)(sm + SM_B);

    for (int kc = 0; kc < 8; kc++) {
        int buf = kc & 1;
        if (kc == 7) cp_wait0(); else cp_wait1();
        __syncthreads();

        const __nv_bfloat16* Ab = Asm + buf * (CHB / 2);
        const __nv_bfloat16* Bb = Bsm + buf * (CHB / 2);
        #pragma unroll
        for (int kf = 0; kf < 4; kf++) {
            wmma::fragment<wmma::matrix_a, 16, 16, 16, __nv_bfloat16, wmma::row_major> a[4];
            #pragma unroll
            for (int i = 0; i < 4; i++)
                wmma::load_matrix_sync(a[i], Ab + (warpM * 64 + i * 16) * LDP + kf * 16, LDP);
            #pragma unroll
            for (int j = 0; j < 2; j++) {
                wmma::fragment<wmma::matrix_b, 16, 16, 16, __nv_bfloat16, wmma::col_major> bfr;
                wmma::load_matrix_sync(bfr, Bb + (warpN * 32 + j * 16) * LDP + kf * 16, LDP);
                #pragma unroll
                for (int i = 0; i < 4; i++)
                    wmma::mma_sync(c[i][j], a[i], bfr, c[i][j]);
            }
        }
        __syncthreads();
        if (kc + 2 < 8) load_chunk(kc + 2, buf);   // buffer now free
    }

    // ---- epilogue: exp(logit + b2) -> fp16 scratch + row sums ----
    __syncthreads();                 // all reads of smem tiles done
    if (tid < 128) rowsum_sm[tid] = 0.f;
    __syncthreads();

    float* buf = stage + wid * 320;  // 16x20 staging per warp
    int r = lane >> 1;
    int cbase = (lane & 1) * 8;
    #pragma unroll
    for (int i = 0; i < 4; i++) {
        #pragma unroll
        for (int j = 0; j < 2; j++) {
            wmma::store_matrix_sync(buf, c[i][j], 20, wmma::mem_row_major);
            __syncwarp();
            int lrow = warpM * 64 + i * 16 + r;
            int grow = m0 + lrow;
            int gcol = n0 + warpN * 32 + j * 16 + cbase;
            float s = 0.f;
            union { __half2 h2[4]; uint4 u4; } uu;
            #pragma unroll
            for (int k2 = 0; k2 < 4; k2++) {
                float e0 = __expf(buf[r * 20 + cbase + 2 * k2]     + __ldg(&b2[gcol + 2 * k2]));
                float e1 = __expf(buf[r * 20 + cbase + 2 * k2 + 1] + __ldg(&b2[gcol + 2 * k2 + 1]));
                s += e0 + e1;
                uu.h2[k2] = __floats2half2_rn(e0, e1);
            }
            *(uint4*)&g_exph[(size_t)grow * V_ + gcol] = uu.u4;
            s += __shfl_xor_sync(0xffffffffu, s, 1);
            if ((lane & 1) == 0) atomicAdd(&rowsum_sm[lrow], s);
            __syncwarp();
        }
    }
    __syncthreads();
    if (tid < 128) atomicAdd(&g_rowsum[m0 + tid], rowsum_sm[tid]);
}

// ===========================================================================
// K5: out = log(p*exph/sum + (1-p)*scatter(attn) + 1e-12)
// ===========================================================================
__device__ __forceinline__ float hash_lookup(int idx, const int* keys, const float* vals) {
    int h = idx & 1023;
    while (keys[h] != idx) h = (h + 1) & 1023;
    return vals[h];
}

__global__ void final_kernel(const float* __restrict__ attn,
                             const int* __restrict__ ebev,
                             float* __restrict__ out) {
    __shared__ unsigned bitmap[1000];
    __shared__ int keys[1024];
    __shared__ float vals[1024];
    int row = blockIdx.x;
    int b = row >> 8;
    int tid = threadIdx.x;
    for (int i = tid; i < 1000; i += 256) bitmap[i] = 0u;
    for (int i = tid; i < 1024; i += 256) { keys[i] = -1; vals[i] = 0.f; }
    __syncthreads();
    float p = g_pgen[row];
    float omp = 1.f - p;
    float scale = p / g_rowsum[row];
    for (int s = tid; s < S_; s += 256) {
        int idx = ebev[b * S_ + s];
        float v = omp * attn[(size_t)row * S_ + s];
        atomicOr(&bitmap[idx >> 5], 1u << (idx & 31));
        int h = idx & 1023;
        while (true) {
            int old = atomicCAS(&keys[h], -1, idx);
            if (old == -1 || old == idx) { atomicAdd(&vals[h], v); break; }
            h = (h + 1) & 1023;
        }
    }
    __syncthreads();
    const uint4* erow = (const uint4*)&g_exph[(size_t)row * V_];
    float4* orow = (float4*)&out[(size_t)row * V_];
    for (int q = tid; q < V_ / 8; q += 256) {
        uint4 e8 = erow[q];
        int vbase = q * 8;
        unsigned w = (bitmap[vbase >> 5] >> (vbase & 31)) & 0xFFu;
        const __half2* hp = (const __half2*)&e8;
        float f[8];
        #pragma unroll
        for (int k = 0; k < 4; k++) {
            float2 fv = __half22float2(hp[k]);
            f[2 * k]     = fv.x * scale + 1e-12f;
            f[2 * k + 1] = fv.y * scale + 1e-12f;
        }
        if (w) {
            #pragma unroll
            for (int k = 0; k < 8; k++)
                if (w & (1u << k)) f[k] += hash_lookup(vbase + k, keys, vals);
        }
        orow[2 * q]     = make_float4(__logf(f[0]), __logf(f[1]), __logf(f[2]), __logf(f[3]));
        orow[2 * q + 1] = make_float4(__logf(f[4]), __logf(f[5]), __logf(f[6]), __logf(f[7]));
    }
}

// ===========================================================================
extern "C" void kernel_launch(void* const* d_in, const int* in_sizes, int n_in,
                              void* d_out, int out_size) {
    const float* s_output = (const float*)d_in[0];
    const float* state    = (const float*)d_in[1];
    const float* attn     = (const float*)d_in[2];
    const int*   ebev     = (const int*)d_in[3];
    const float* w_pgen   = (const float*)d_in[4];
    const float* b_pgen   = (const float*)d_in[5];
    const float* w1       = (const float*)d_in[6];
    const float* b1       = (const float*)d_in[7];
    const float* w2       = (const float*)d_in[8];
    const float* b2       = (const float*)d_in[9];
    float* out = (float*)d_out;

    cudaFuncSetAttribute(logits_wmma_kernel,
                         cudaFuncAttributeMaxDynamicSharedMemorySize, GSMEM);

    pgen_kernel<<<R_ / 8, 256>>>(state, w_pgen, b_pgen);
    transpose_w2_kernel<<<dim3(V_ / 32, H_ / 32), 256>>>(w2);
    hidden_kernel<<<dim3(H_ / 64, R_ / 64), 256>>>(s_output, w1, b1);
    logits_wmma_kernel<<<dim3(V_ / 128, R_ / 128), 256, GSMEM>>>(b2);
    final_kernel<<<R_, 256>>>(attn, ebev, out);
}

// round 9
// speedup vs baseline: 1.6711x; 1.2090x over previous
#include <cuda_runtime.h>
#include <cuda_bf16.h>
#include <cuda_fp16.h>
#include <mma.h>
#include <cstdint>

using namespace nvcuda;

#define B_ 8
#define T_ 256
#define S_ 400
#define H_ 512
#define V_ 32000
#define R_ 2048   // B*T rows

// ---- scratch (no cudaMalloc allowed -> __device__ globals) ----
__device__ __half          g_exph[(size_t)R_ * V_];   // 131 MB: exp(logits) fp16
__device__ __nv_bfloat16   g_w2t[(size_t)V_ * H_];    // 32.8 MB: w2 transposed [V][H] bf16
__device__ __nv_bfloat16   g_hidden[R_ * H_];         // 2 MB: bf16 hidden
__device__ float           g_pgen[R_];
__device__ float           g_rowsum[R_];

// ---- cp.async helpers ----
__device__ __forceinline__ uint32_t smem_u32(const void* p) {
    uint32_t a;
    asm("{ .reg .u64 t; cvta.to.shared.u64 t, %1; cvt.u32.u64 %0, t; }" : "=r"(a) : "l"(p));
    return a;
}
__device__ __forceinline__ void cp16(uint32_t dst, const void* src) {
    asm volatile("cp.async.cg.shared.global [%0], [%1], 16;" :: "r"(dst), "l"(src));
}
__device__ __forceinline__ void cp_commit() { asm volatile("cp.async.commit_group;"); }
__device__ __forceinline__ void cp_wait1() { asm volatile("cp.async.wait_group 1;" ::: "memory"); }
__device__ __forceinline__ void cp_wait0() { asm volatile("cp.async.wait_group 0;" ::: "memory"); }

// ===========================================================================
// K1: p_gen = sigmoid(state_input @ w_pgen + b_pgen); zero row sums.
// ===========================================================================
__global__ void pgen_kernel(const float* __restrict__ state,
                            const float* __restrict__ wp,
                            const float* __restrict__ bp) {
    int row  = blockIdx.x * 8 + (threadIdx.x >> 5);
    int lane = threadIdx.x & 31;
    const float* x = state + (size_t)row * (2 * H_);
    float s = 0.f;
    #pragma unroll 8
    for (int i = lane; i < 2 * H_; i += 32) s += x[i] * wp[i];
    #pragma unroll
    for (int o = 16; o; o >>= 1) s += __shfl_xor_sync(0xffffffffu, s, o);
    if (lane == 0) {
        float z = s + bp[0];
        g_pgen[row]   = 1.f / (1.f + __expf(-z));
        g_rowsum[row] = 0.f;
    }
}

// ===========================================================================
// K2: transpose w2 [H][V] fp32 -> g_w2t [V][H] bf16 (K-major B for the GEMM)
// ===========================================================================
__global__ void transpose_w2_kernel(const float* __restrict__ w2) {
    __shared__ float tile[32][33];
    int c0 = blockIdx.x * 32;   // vocab base
    int r0 = blockIdx.y * 32;   // H base
    int tx = threadIdx.x & 31, ty = threadIdx.x >> 5;  // 32 x 8
    #pragma unroll
    for (int i = 0; i < 4; i++)
        tile[ty + i * 8][tx] = w2[(size_t)(r0 + ty + i * 8) * V_ + c0 + tx];
    __syncthreads();
    #pragma unroll
    for (int i = 0; i < 4; i++)
        g_w2t[(size_t)(c0 + ty + i * 8) * H_ + r0 + tx] =
            __float2bfloat16(tile[tx][ty + i * 8]);
}

// ===========================================================================
// K3: hidden = s_output @ w1 + b1  (2048x512x512) -- WMMA bf16, fp32 accum.
// 64x64 tile, 128 threads (4 warps, each 32x32), in-kernel fp32->bf16.
// ===========================================================================
#define HLD 72
__global__ void __launch_bounds__(128)
hidden_wmma_kernel(const float* __restrict__ A,
                   const float* __restrict__ W,
                   const float* __restrict__ b1) {
    __shared__ __nv_bfloat16 As[64 * HLD];
    __shared__ __nv_bfloat16 Bs[64 * HLD];
    int tid = threadIdx.x, wid = tid >> 5, lane = tid & 31;
    int warpM = wid >> 1, warpN = wid & 1;
    int m0 = blockIdx.y * 64, n0 = blockIdx.x * 64;

    wmma::fragment<wmma::accumulator, 16, 16, 16, float> c[2][2];
    #pragma unroll
    for (int i = 0; i < 2; i++)
        #pragma unroll
        for (int j = 0; j < 2; j++) wmma::fill_fragment(c[i][j], 0.f);

    for (int kc = 0; kc < 8; kc++) {
        __syncthreads();
        #pragma unroll
        for (int h = 0; h < 8; h++) {
            int idx = tid + h * 128;          // 0..1023 float4 slots
            int r = idx >> 4, c4 = idx & 15;
            float4 v = *(const float4*)&A[(size_t)(m0 + r) * H_ + kc * 64 + c4 * 4];
            __nv_bfloat162* d2 = (__nv_bfloat162*)&As[r * HLD + c4 * 4];
            d2[0] = __floats2bfloat162_rn(v.x, v.y);
            d2[1] = __floats2bfloat162_rn(v.z, v.w);
        }
        #pragma unroll
        for (int h = 0; h < 8; h++) {
            int idx = tid + h * 128;
            int r = idx >> 4, c4 = idx & 15;
            float4 v = *(const float4*)&W[(size_t)(kc * 64 + r) * H_ + n0 + c4 * 4];
            __nv_bfloat162* d2 = (__nv_bfloat162*)&Bs[r * HLD + c4 * 4];
            d2[0] = __floats2bfloat162_rn(v.x, v.y);
            d2[1] = __floats2bfloat162_rn(v.z, v.w);
        }
        __syncthreads();
        #pragma unroll
        for (int kf = 0; kf < 4; kf++) {
            wmma::fragment<wmma::matrix_a, 16, 16, 16, __nv_bfloat16, wmma::row_major> a[2];
            wmma::fragment<wmma::matrix_b, 16, 16, 16, __nv_bfloat16, wmma::row_major> b[2];
            #pragma unroll
            for (int i = 0; i < 2; i++)
                wmma::load_matrix_sync(a[i], As + (warpM * 32 + i * 16) * HLD + kf * 16, HLD);
            #pragma unroll
            for (int j = 0; j < 2; j++)
                wmma::load_matrix_sync(b[j], Bs + (kf * 16) * HLD + warpN * 32 + j * 16, HLD);
            #pragma unroll
            for (int i = 0; i < 2; i++)
                #pragma unroll
                for (int j = 0; j < 2; j++)
                    wmma::mma_sync(c[i][j], a[i], b[j], c[i][j]);
        }
    }
    __syncthreads();
    float* buf = (float*)As + wid * 320;      // 16x20 per-warp staging
    int r = lane >> 1, cbase = (lane & 1) * 8;
    #pragma unroll
    for (int i = 0; i < 2; i++)
        #pragma unroll
        for (int j = 0; j < 2; j++) {
            wmma::store_matrix_sync(buf, c[i][j], 20, wmma::mem_row_major);
            __syncwarp();
            int row = m0 + warpM * 32 + i * 16 + r;
            int col = n0 + warpN * 32 + j * 16 + cbase;
            union { __nv_bfloat162 b2v[4]; uint4 u4; } uu;
            #pragma unroll
            for (int k2 = 0; k2 < 4; k2++)
                uu.b2v[k2] = __floats2bfloat162_rn(
                    buf[r * 20 + cbase + 2 * k2]     + b1[col + 2 * k2],
                    buf[r * 20 + cbase + 2 * k2 + 1] + b1[col + 2 * k2 + 1]);
            *(uint4*)&g_hidden[(size_t)row * H_ + col] = uu.u4;
            __syncwarp();
        }
}

// ===========================================================================
// K4: WMMA GEMM (2048 x 32000 x 512, bf16, fp32 accum) + fused epilogue.
// CTA tile 128x128, BK=64, 3-stage cp.async ring, ONE __syncthreads per
// chunk. 8 warps (2Mx4N), warp tile 64x32. ld = 72 (conflict-free ldmatrix).
// ===========================================================================
#define LDP  72
#define CHB  (128 * LDP * 2)          // 18432 B per tile buffer
#define SM_A 0                        // 3 buffers A
#define SM_B (3 * CHB)                // 3 buffers B
#define GSMEM (6 * CHB)               // 110592 B

__global__ void __launch_bounds__(256, 2)
logits_wmma_kernel(const float* __restrict__ b2) {
    extern __shared__ char sm[];
    uint32_t sb = smem_u32(sm);
    float* stage = (float*)sm;                   // epilogue reuse
    float* rowsum_sm = (float*)(sm + 10240);

    int tid = threadIdx.x, wid = tid >> 5, lane = tid & 31;
    int warpM = wid >> 2, warpN = wid & 3;
    int n0 = blockIdx.x * 128, m0 = blockIdx.y * 128;

    wmma::fragment<wmma::accumulator, 16, 16, 16, float> c[4][2];
    #pragma unroll
    for (int i = 0; i < 4; i++)
        #pragma unroll
        for (int j = 0; j < 2; j++) wmma::fill_fragment(c[i][j], 0.f);

    auto load_chunk = [&](int kc, int buf) {
        #pragma unroll
        for (int h = 0; h < 4; h++) {
            int idx = tid + h * 256;             // 0..1023
            int r = idx >> 3, c16 = idx & 7;
            cp16(sb + SM_A + buf * CHB + r * (LDP * 2) + c16 * 16,
                 &g_hidden[(size_t)(m0 + r) * H_ + kc * 64 + c16 * 8]);
        }
        #pragma unroll
        for (int h = 0; h < 4; h++) {
            int idx = tid + h * 256;
            int r = idx >> 3, c16 = idx & 7;
            cp16(sb + SM_B + buf * CHB + r * (LDP * 2) + c16 * 16,
                 &g_w2t[(size_t)(n0 + r) * H_ + kc * 64 + c16 * 8]);
        }
        cp_commit();
    };

    load_chunk(0, 0);
    load_chunk(1, 1);

    const __nv_bfloat16* Asm = (const __nv_bfloat16*)(sm + SM_A);
    const __nv_bfloat16* Bsm = (const __nv_bfloat16*)(sm + SM_B);

    for (int kc = 0; kc < 8; kc++) {
        if (kc == 7) cp_wait0(); else cp_wait1();   // chunk kc resident
        __syncthreads();                            // data visible; prev compute done
        if (kc + 2 < 8) load_chunk(kc + 2, (kc + 2) % 3);

        int buf = kc % 3;
        const __nv_bfloat16* Ab = Asm + buf * (CHB / 2);
        const __nv_bfloat16* Bb = Bsm + buf * (CHB / 2);
        #pragma unroll
        for (int kf = 0; kf < 4; kf++) {
            wmma::fragment<wmma::matrix_a, 16, 16, 16, __nv_bfloat16, wmma::row_major> a[4];
            #pragma unroll
            for (int i = 0; i < 4; i++)
                wmma::load_matrix_sync(a[i], Ab + (warpM * 64 + i * 16) * LDP + kf * 16, LDP);
            #pragma unroll
            for (int j = 0; j < 2; j++) {
                wmma::fragment<wmma::matrix_b, 16, 16, 16, __nv_bfloat16, wmma::col_major> bfr;
                wmma::load_matrix_sync(bfr, Bb + (warpN * 32 + j * 16) * LDP + kf * 16, LDP);
                #pragma unroll
                for (int i = 0; i < 4; i++)
                    wmma::mma_sync(c[i][j], a[i], bfr, c[i][j]);
            }
        }
    }

    // ---- epilogue: exp(logit + b2) -> fp16 scratch (streaming) + row sums ----
    __syncthreads();
    if (tid < 128) rowsum_sm[tid] = 0.f;
    __syncthreads();

    float* buf = stage + wid * 320;  // 16x20 staging per warp
    int r = lane >> 1;
    int cbase = (lane & 1) * 8;
    #pragma unroll
    for (int i = 0; i < 4; i++) {
        #pragma unroll
        for (int j = 0; j < 2; j++) {
            wmma::store_matrix_sync(buf, c[i][j], 20, wmma::mem_row_major);
            __syncwarp();
            int lrow = warpM * 64 + i * 16 + r;
            int grow = m0 + lrow;
            int gcol = n0 + warpN * 32 + j * 16 + cbase;
            float s = 0.f;
            union { __half2 h2[4]; uint4 u4; } uu;
            #pragma unroll
            for (int k2 = 0; k2 < 4; k2++) {
                float e0 = __expf(buf[r * 20 + cbase + 2 * k2]     + __ldg(&b2[gcol + 2 * k2]));
                float e1 = __expf(buf[r * 20 + cbase + 2 * k2 + 1] + __ldg(&b2[gcol + 2 * k2 + 1]));
                s += e0 + e1;
                uu.h2[k2] = __floats2half2_rn(e0, e1);
            }
            __stcs((uint4*)&g_exph[(size_t)grow * V_ + gcol], uu.u4);
            s += __shfl_xor_sync(0xffffffffu, s, 1);
            if ((lane & 1) == 0) atomicAdd(&rowsum_sm[lrow], s);
            __syncwarp();
        }
    }
    __syncthreads();
    if (tid < 128) atomicAdd(&g_rowsum[m0 + tid], rowsum_sm[tid]);
}

// ===========================================================================
// K5: out = log(p*exph/sum + (1-p)*scatter(attn) + 1e-12)
// ===========================================================================
__device__ __forceinline__ float hash_lookup(int idx, const int* keys, const float* vals) {
    int h = idx & 1023;
    while (keys[h] != idx) h = (h + 1) & 1023;
    return vals[h];
}

__global__ void final_kernel(const float* __restrict__ attn,
                             const int* __restrict__ ebev,
                             float* __restrict__ out) {
    __shared__ unsigned bitmap[1000];
    __shared__ int keys[1024];
    __shared__ float vals[1024];
    int row = blockIdx.x;
    int b = row >> 8;
    int tid = threadIdx.x;
    for (int i = tid; i < 1000; i += 256) bitmap[i] = 0u;
    for (int i = tid; i < 1024; i += 256) { keys[i] = -1; vals[i] = 0.f; }
    __syncthreads();
    float p = g_pgen[row];
    float omp = 1.f - p;
    float scale = p / g_rowsum[row];
    for (int s = tid; s < S_; s += 256) {
        int idx = ebev[b * S_ + s];
        float v = omp * attn[(size_t)row * S_ + s];
        atomicOr(&bitmap[idx >> 5], 1u << (idx & 31));
        int h = idx & 1023;
        while (true) {
            int old = atomicCAS(&keys[h], -1, idx);
            if (old == -1 || old == idx) { atomicAdd(&vals[h], v); break; }
            h = (h + 1) & 1023;
        }
    }
    __syncthreads();
    const uint4* erow = (const uint4*)&g_exph[(size_t)row * V_];
    float4* orow = (float4*)&out[(size_t)row * V_];
    for (int q = tid; q < V_ / 8; q += 256) {
        uint4 e8 = __ldcs(&erow[q]);
        int vbase = q * 8;
        unsigned w = (bitmap[vbase >> 5] >> (vbase & 31)) & 0xFFu;
        const __half2* hp = (const __half2*)&e8;
        float f[8];
        #pragma unroll
        for (int k = 0; k < 4; k++) {
            float2 fv = __half22float2(hp[k]);
            f[2 * k]     = fv.x * scale + 1e-12f;
            f[2 * k + 1] = fv.y * scale + 1e-12f;
        }
        if (w) {
            #pragma unroll
            for (int k = 0; k < 8; k++)
                if (w & (1u << k)) f[k] += hash_lookup(vbase + k, keys, vals);
        }
        __stcs(&orow[2 * q],     make_float4(__logf(f[0]), __logf(f[1]), __logf(f[2]), __logf(f[3])));
        __stcs(&orow[2 * q + 1], make_float4(__logf(f[4]), __logf(f[5]), __logf(f[6]), __logf(f[7])));
    }
}

// ===========================================================================
extern "C" void kernel_launch(void* const* d_in, const int* in_sizes, int n_in,
                              void* d_out, int out_size) {
    const float* s_output = (const float*)d_in[0];
    const float* state    = (const float*)d_in[1];
    const float* attn     = (const float*)d_in[2];
    const int*   ebev     = (const int*)d_in[3];
    const float* w_pgen   = (const float*)d_in[4];
    const float* b_pgen   = (const float*)d_in[5];
    const float* w1       = (const float*)d_in[6];
    const float* b1       = (const float*)d_in[7];
    const float* w2       = (const float*)d_in[8];
    const float* b2       = (const float*)d_in[9];
    float* out = (float*)d_out;

    cudaFuncSetAttribute(logits_wmma_kernel,
                         cudaFuncAttributeMaxDynamicSharedMemorySize, GSMEM);

    pgen_kernel<<<R_ / 8, 256>>>(state, w_pgen, b_pgen);
    transpose_w2_kernel<<<dim3(V_ / 32, H_ / 32), 256>>>(w2);
    hidden_wmma_kernel<<<dim3(H_ / 64, R_ / 64), 128>>>(s_output, w1, b1);
    logits_wmma_kernel<<<dim3(V_ / 128, R_ / 128), 256, GSMEM>>>(b2);
    final_kernel<<<R_, 256>>>(attn, ebev, out);
}